// round 1
// baseline (speedup 1.0000x reference)
#include <cuda_runtime.h>
#include <cuda_bf16.h>
#include <math.h>

// Problem constants
#define B_  4
#define T_  2048
#define D_  1024
#define H_  16
#define HD_ 64
#define BT  (B_ * T_)            // 8192
#define BH  (B_ * H_)            // 64

// ---------------- scratch (device globals; no allocation allowed) ----------
__device__ float g_qkv[(size_t)BT * (3 * D_)];          // 96 MB
__device__ float g_q  [(size_t)BH * T_ * HD_];           // 33.5 MB
__device__ float g_k  [(size_t)BH * T_ * HD_];
__device__ float g_v  [(size_t)BH * T_ * HD_];
__device__ float g_pv [(size_t)BH * T_ * HD_];           // PV output [b,h,t,d]
__device__ float g_ctx[(size_t)BT * D_];                 // merged heads [b,t,h*d]
__device__ float g_S  [(size_t)BH * T_ * T_];            // 1 GB scores
__device__ float g_sin[T_ * (HD_ / 2)];
__device__ float g_cos[T_ * (HD_ / 2)];

// ---------------- RoPE tables (double precision, tiny) ---------------------
__global__ void rope_tables_kernel() {
    int idx = blockIdx.x * blockDim.x + threadIdx.x;   // t*32 + j
    if (idx >= T_ * (HD_ / 2)) return;
    int j = idx & 31;
    int t = idx >> 5;
    double theta = pow(1000.0, -2.0 * (double)(j + 1) / (double)HD_);
    double ang = (double)(t + 1) * theta;
    g_sin[idx] = (float)sin(ang);
    g_cos[idx] = (float)cos(ang);
}

// ---------------- split heads + RoPE ---------------------------------------
__global__ void rope_apply_kernel() {
    int idx = blockIdx.x * blockDim.x + threadIdx.x;   // (b,t,h,j), total 4.19M
    int j = idx & 31;
    int h = (idx >> 5) & 15;
    int t = (idx >> 9) & 2047;
    int b = idx >> 20;
    size_t base = (size_t)(b * T_ + t) * (3 * D_);
    int c = h * HD_ + 2 * j;
    float q0 = g_qkv[base + c],            q1 = g_qkv[base + c + 1];
    float k0 = g_qkv[base + D_ + c],       k1 = g_qkv[base + D_ + c + 1];
    float v0 = g_qkv[base + 2 * D_ + c],   v1 = g_qkv[base + 2 * D_ + c + 1];
    float sn = g_sin[t * 32 + j];
    float cs = g_cos[t * 32 + j];
    size_t o = ((size_t)(b * H_ + h) * T_ + t) * HD_ + 2 * j;
    g_q[o]     = q0 * cs - q1 * sn;
    g_q[o + 1] = q1 * cs + q0 * sn;
    g_k[o]     = k0 * cs - k1 * sn;
    g_k[o + 1] = k1 * cs + k0 * sn;
    g_v[o]     = v0;
    g_v[o + 1] = v1;
}

// ---------------- generic tiled SGEMM ---------------------------------------
// C[z] = alpha * A[z] @ op(B[z]) (+ bias).  All dims divisible by tile sizes.
#define BM 128
#define BN 64
#define BK 16
#define TM 8
#define TN 4
// 256 threads/block

template<bool TRANSB, bool HAS_BIAS>
__global__ __launch_bounds__(256)
void sgemm_kernel(const float* __restrict__ A, const float* __restrict__ Bm,
                  const float* __restrict__ bias, float* __restrict__ C,
                  int K, int lda, int ldb, int ldc,
                  long sA, long sB, long sC, float alpha)
{
    const int z = blockIdx.z;
    A  += (size_t)z * sA;
    Bm += (size_t)z * sB;
    C  += (size_t)z * sC;
    const int bm = blockIdx.y * BM;
    const int bn = blockIdx.x * BN;

    __shared__ float As[BK][BM + 4];
    __shared__ float Bs[BK][BN];

    const int tid  = threadIdx.x;
    const int tx   = tid & 15;     // N direction
    const int ty   = tid >> 4;     // M direction
    const int row0 = ty * TM;
    const int col0 = tx * TN;

    float acc[TM][TN];
    #pragma unroll
    for (int i = 0; i < TM; i++)
        #pragma unroll
        for (int j = 0; j < TN; j++) acc[i][j] = 0.f;

    for (int k0 = 0; k0 < K; k0 += BK) {
        // A tile: BM x BK, float4 along K, stored transposed
        #pragma unroll
        for (int i = 0; i < 2; i++) {
            int idx4 = tid + i * 256;          // 0..511
            int m    = idx4 >> 2;              // 0..127
            int kk   = (idx4 & 3) * 4;         // 0,4,8,12
            const float4 av = *reinterpret_cast<const float4*>(
                &A[(size_t)(bm + m) * lda + k0 + kk]);
            As[kk + 0][m] = av.x;
            As[kk + 1][m] = av.y;
            As[kk + 2][m] = av.z;
            As[kk + 3][m] = av.w;
        }
        // B tile
        if (TRANSB) {
            // Bs[k][n] = B[(bn+n)*ldb + k0+k]
            int n  = tid >> 2;                 // 0..63
            int kk = (tid & 3) * 4;
            const float4 bv = *reinterpret_cast<const float4*>(
                &Bm[(size_t)(bn + n) * ldb + k0 + kk]);
            Bs[kk + 0][n] = bv.x;
            Bs[kk + 1][n] = bv.y;
            Bs[kk + 2][n] = bv.z;
            Bs[kk + 3][n] = bv.w;
        } else {
            // Bs[k][n] = B[(k0+k)*ldb + bn+n]
            int kk = tid >> 4;                 // 0..15
            int n  = (tid & 15) * 4;           // 0..60
            const float4 bv = *reinterpret_cast<const float4*>(
                &Bm[(size_t)(k0 + kk) * ldb + bn + n]);
            *reinterpret_cast<float4*>(&Bs[kk][n]) = bv;
        }
        __syncthreads();

        #pragma unroll
        for (int k = 0; k < BK; k++) {
            float a[TM], b[TN];
            #pragma unroll
            for (int i = 0; i < TM; i++) a[i] = As[k][row0 + i];
            #pragma unroll
            for (int j = 0; j < TN; j++) b[j] = Bs[k][col0 + j];
            #pragma unroll
            for (int i = 0; i < TM; i++)
                #pragma unroll
                for (int j = 0; j < TN; j++)
                    acc[i][j] = fmaf(a[i], b[j], acc[i][j]);
        }
        __syncthreads();
    }

    #pragma unroll
    for (int i = 0; i < TM; i++) {
        #pragma unroll
        for (int j = 0; j < TN; j++) {
            float v = acc[i][j] * alpha;
            if (HAS_BIAS) v += bias[bn + col0 + j];
            C[(size_t)(bm + row0 + i) * ldc + bn + col0 + j] = v;
        }
    }
}

// ---------------- row softmax (row length 2048, 256 threads) ---------------
__global__ __launch_bounds__(256)
void softmax_kernel() {
    const size_t row = blockIdx.x;
    float* p = g_S + row * (size_t)T_;
    const int tid = threadIdx.x;

    float v[8];
    float mx = -INFINITY;
    #pragma unroll
    for (int i = 0; i < 8; i++) {
        v[i] = p[tid + i * 256];
        mx = fmaxf(mx, v[i]);
    }
    __shared__ float red[8];
    #pragma unroll
    for (int o = 16; o > 0; o >>= 1) mx = fmaxf(mx, __shfl_xor_sync(~0u, mx, o));
    if ((tid & 31) == 0) red[tid >> 5] = mx;
    __syncthreads();
    mx = fmaxf(fmaxf(fmaxf(red[0], red[1]), fmaxf(red[2], red[3])),
               fmaxf(fmaxf(red[4], red[5]), fmaxf(red[6], red[7])));
    __syncthreads();

    float sum = 0.f;
    #pragma unroll
    for (int i = 0; i < 8; i++) {
        v[i] = __expf(v[i] - mx);
        sum += v[i];
    }
    #pragma unroll
    for (int o = 16; o > 0; o >>= 1) sum += __shfl_xor_sync(~0u, sum, o);
    if ((tid & 31) == 0) red[tid >> 5] = sum;
    __syncthreads();
    sum = red[0] + red[1] + red[2] + red[3] + red[4] + red[5] + red[6] + red[7];

    const float inv = 1.f / sum;
    #pragma unroll
    for (int i = 0; i < 8; i++) p[tid + i * 256] = v[i] * inv;
}

// ---------------- merge heads: [b,h,t,d] -> [b,t,h*d] -----------------------
__global__ __launch_bounds__(256)
void merge_heads_kernel() {
    int idx = blockIdx.x * blockDim.x + threadIdx.x;   // b,t,h,d (d fastest)
    int d = idx & 63;
    int h = (idx >> 6) & 15;
    int t = (idx >> 10) & 2047;
    int b = idx >> 21;
    g_ctx[idx] = g_pv[((size_t)(b * H_ + h) * T_ + t) * HD_ + d];
}

// ---------------- launch ----------------------------------------------------
extern "C" void kernel_launch(void* const* d_in, const int* in_sizes, int n_in,
                              void* d_out, int out_size)
{
    const float* x      = (const float*)d_in[0];
    const float* W_attn = (const float*)d_in[1];
    const float* b_attn = (const float*)d_in[2];
    const float* W_proj = (const float*)d_in[3];
    const float* b_proj = (const float*)d_in[4];
    float* out = (float*)d_out;

    float *qkv, *q, *k, *v, *pv, *ctx, *S;
    cudaGetSymbolAddress((void**)&qkv, g_qkv);
    cudaGetSymbolAddress((void**)&q,   g_q);
    cudaGetSymbolAddress((void**)&k,   g_k);
    cudaGetSymbolAddress((void**)&v,   g_v);
    cudaGetSymbolAddress((void**)&pv,  g_pv);
    cudaGetSymbolAddress((void**)&ctx, g_ctx);
    cudaGetSymbolAddress((void**)&S,   g_S);

    // 1. RoPE sin/cos tables
    rope_tables_kernel<<<(T_ * 32) / 256, 256>>>();

    // 2. QKV GEMM: [8192,1024] @ [1024,3072] + b_attn
    {
        dim3 grid(3 * D_ / BN, BT / BM, 1);
        sgemm_kernel<false, true><<<grid, 256>>>(
            x, W_attn, b_attn, qkv,
            D_, D_, 3 * D_, 3 * D_, 0, 0, 0, 1.0f);
    }

    // 3. split heads + RoPE
    rope_apply_kernel<<<(B_ * T_ * H_ * 32) / 256, 256>>>();

    // 4. scores: S[z] = q[z] @ k[z]^T / sqrt(512), z = b*H+h
    {
        dim3 grid(T_ / BN, T_ / BM, BH);
        sgemm_kernel<true, false><<<grid, 256>>>(
            q, k, nullptr, S,
            HD_, HD_, HD_, T_,
            (long)T_ * HD_, (long)T_ * HD_, (long)T_ * T_,
            0.044194173824159216f);  // 1/sqrt(512)
    }

    // 5. softmax rows
    softmax_kernel<<<BH * T_, 256>>>();

    // 6. PV: O[z] = P[z] @ V[z]
    {
        dim3 grid(HD_ / BN, T_ / BM, BH);
        sgemm_kernel<false, false><<<grid, 256>>>(
            S, v, nullptr, pv,
            T_, T_, HD_, HD_,
            (long)T_ * T_, (long)T_ * HD_, (long)T_ * HD_, 1.0f);
    }

    // 7. merge heads
    merge_heads_kernel<<<(BT * D_) / 256, 256>>>();

    // 8. output projection: [8192,1024] @ [1024,1024] + b_proj
    {
        dim3 grid(D_ / BN, BT / BM, 1);
        sgemm_kernel<false, true><<<grid, 256>>>(
            ctx, W_proj, b_proj, out,
            D_, D_, D_, D_, 0, 0, 0, 1.0f);
    }
}

// round 2
// speedup vs baseline: 2.3890x; 2.3890x over previous
#include <cuda_runtime.h>
#include <cuda_bf16.h>
#include <math.h>
#include <stdint.h>

// Problem constants
#define B_  4
#define T_  2048
#define D_  1024
#define H_  16
#define HD_ 64
#define BT  (B_ * T_)            // 8192
#define BH  (B_ * H_)            // 64

// ---------------- scratch (device globals; no allocation allowed) ----------
__device__ float g_qkv[(size_t)BT * (3 * D_)];
__device__ float g_q  [(size_t)BH * T_ * HD_];
__device__ float g_k  [(size_t)BH * T_ * HD_];
__device__ float g_v  [(size_t)BH * T_ * HD_];
__device__ float g_pv [(size_t)BH * T_ * HD_];
__device__ float g_ctx[(size_t)BT * D_];
__device__ float g_S  [(size_t)BH * T_ * T_];           // 1 GB scores
__device__ float g_sin[T_ * (HD_ / 2)];
__device__ float g_cos[T_ * (HD_ / 2)];
__device__ float g_xr [(size_t)BT * D_];                // tf32-rounded x
__device__ float g_war[(size_t)D_ * 3 * D_];            // tf32-rounded W_attn
__device__ float g_wpr[(size_t)D_ * D_];                // tf32-rounded W_proj

// ---------------- helpers ----------------------------------------------------
__device__ __forceinline__ float tf32r(float x) {
    float y;
    asm("cvt.rna.tf32.f32 %0, %1;" : "=f"(y) : "f"(x));
    return y;
}

__device__ __forceinline__ void cp_async16(void* smem, const void* gmem) {
    uint32_t s = (uint32_t)__cvta_generic_to_shared(smem);
    asm volatile("cp.async.cg.shared.global [%0], [%1], 16;\n" :: "r"(s), "l"(gmem));
}

__device__ __forceinline__ void mma_tf32(float c[4],
    uint32_t a0, uint32_t a1, uint32_t a2, uint32_t a3,
    uint32_t b0, uint32_t b1)
{
    asm volatile(
        "mma.sync.aligned.m16n8k8.row.col.f32.tf32.tf32.f32 "
        "{%0,%1,%2,%3}, {%4,%5,%6,%7}, {%8,%9}, {%0,%1,%2,%3};\n"
        : "+f"(c[0]), "+f"(c[1]), "+f"(c[2]), "+f"(c[3])
        : "r"(a0), "r"(a1), "r"(a2), "r"(a3), "r"(b0), "r"(b1));
}

// ---------------- RoPE tables -----------------------------------------------
__global__ void rope_tables_kernel() {
    int idx = blockIdx.x * blockDim.x + threadIdx.x;
    if (idx >= T_ * (HD_ / 2)) return;
    int j = idx & 31;
    int t = idx >> 5;
    double theta = pow(1000.0, -2.0 * (double)(j + 1) / (double)HD_);
    double ang = (double)(t + 1) * theta;
    g_sin[idx] = (float)sin(ang);
    g_cos[idx] = (float)cos(ang);
}

// ---------------- tf32-round copy -------------------------------------------
__global__ void round_copy_kernel(const float4* __restrict__ src,
                                  float4* __restrict__ dst, int n4) {
    int i = blockIdx.x * blockDim.x + threadIdx.x;
    if (i >= n4) return;
    float4 v = src[i];
    v.x = tf32r(v.x); v.y = tf32r(v.y); v.z = tf32r(v.z); v.w = tf32r(v.w);
    dst[i] = v;
}

// ---------------- split heads + RoPE (outputs tf32-rounded) -----------------
__global__ void rope_apply_kernel() {
    int idx = blockIdx.x * blockDim.x + threadIdx.x;
    int j = idx & 31;
    int h = (idx >> 5) & 15;
    int t = (idx >> 9) & 2047;
    int b = idx >> 20;
    size_t base = (size_t)(b * T_ + t) * (3 * D_);
    int c = h * HD_ + 2 * j;
    float q0 = g_qkv[base + c],            q1 = g_qkv[base + c + 1];
    float k0 = g_qkv[base + D_ + c],       k1 = g_qkv[base + D_ + c + 1];
    float v0 = g_qkv[base + 2 * D_ + c],   v1 = g_qkv[base + 2 * D_ + c + 1];
    float sn = g_sin[t * 32 + j];
    float cs = g_cos[t * 32 + j];
    size_t o = ((size_t)(b * H_ + h) * T_ + t) * HD_ + 2 * j;
    g_q[o]     = tf32r(q0 * cs - q1 * sn);
    g_q[o + 1] = tf32r(q1 * cs + q0 * sn);
    g_k[o]     = tf32r(k0 * cs - k1 * sn);
    g_k[o + 1] = tf32r(k1 * cs + k0 * sn);
    g_v[o]     = tf32r(v0);
    g_v[o + 1] = tf32r(v1);
}

// ---------------- TF32 tensor-core GEMM --------------------------------------
// C[z] = alpha * A[z] @ op(B[z]) (+ bias).  Row-major A [M,K].
// TRANSB: B row-major [N,K] (C = A B^T); else B row-major [K,N].
// Block tile BM x BN, BK=32. Warp tile 64x32 (2x4 m16n8k8 tiles x 4 ksteps).
template<int BM, int BN, int THREADS, bool TRANSB, bool HAS_BIAS>
__global__ __launch_bounds__(THREADS)
void tgemm(const float* __restrict__ A, const float* __restrict__ Bm,
           const float* __restrict__ bias, float* __restrict__ C,
           int K, int lda, int ldb, int ldc,
           long sA, long sB, long sC, float alpha)
{
    constexpr int BK = 32;
    constexpr int WM = 64, WN = 32;
    constexpr int WARPS_M = BM / WM;
    constexpr int WARPS_N = BN / WN;
    static_assert(WARPS_M * WARPS_N * 32 == THREADS, "thread count");
    constexpr int AP = 4;                       // pad -> stride 36 words
    constexpr int A_SZ = BM * (BK + AP);
    constexpr int B_SZ = TRANSB ? BN * (BK + AP) : BK * (BN + 8);
    constexpr int STG = A_SZ + B_SZ;

    extern __shared__ float sm[];

    const int z = blockIdx.z;
    A  += (size_t)z * sA;
    Bm += (size_t)z * sB;
    C  += (size_t)z * sC;
    const int bm = blockIdx.y * BM;
    const int bn = blockIdx.x * BN;

    const int tid  = threadIdx.x;
    const int warp = tid >> 5;
    const int lane = tid & 31;
    const int grp  = lane >> 2;     // 0..7
    const int qd   = lane & 3;      // 0..3
    const int wm   = (warp % WARPS_M) * WM;
    const int wn   = (warp / WARPS_M) * WN;

    float acc[4][4][4];
    #pragma unroll
    for (int i = 0; i < 4; i++)
        #pragma unroll
        for (int j = 0; j < 4; j++)
            #pragma unroll
            for (int r = 0; r < 4; r++) acc[i][j][r] = 0.f;

    auto load_tiles = [&](int k0, int s) {
        float* as = sm + s * STG;
        float* bs = as + A_SZ;
        constexpr int A_IT = (BM * 8) / THREADS;
        #pragma unroll
        for (int i = 0; i < A_IT; i++) {
            int v  = tid + i * THREADS;
            int m  = v >> 3;
            int kq = (v & 7) * 4;
            cp_async16(&as[m * (BK + AP) + kq],
                       &A[(size_t)(bm + m) * lda + k0 + kq]);
        }
        if (TRANSB) {
            constexpr int B_IT = (BN * 8) / THREADS;
            #pragma unroll
            for (int i = 0; i < B_IT; i++) {
                int v  = tid + i * THREADS;
                int n  = v >> 3;
                int kq = (v & 7) * 4;
                cp_async16(&bs[n * (BK + AP) + kq],
                           &Bm[(size_t)(bn + n) * ldb + k0 + kq]);
            }
        } else {
            constexpr int B_IT = (BK * (BN / 4)) / THREADS;
            #pragma unroll
            for (int i = 0; i < B_IT; i++) {
                int v  = tid + i * THREADS;
                int k  = v / (BN / 4);
                int n4 = (v % (BN / 4)) * 4;
                cp_async16(&bs[k * (BN + 8) + n4],
                           &Bm[(size_t)(k0 + k) * ldb + bn + n4]);
            }
        }
        asm volatile("cp.async.commit_group;\n");
    };

    auto compute = [&](int s) {
        const float* as = sm + s * STG;
        const float* bs = as + A_SZ;
        #pragma unroll
        for (int ks = 0; ks < 4; ks++) {
            const int kb = ks * 8;
            uint32_t af[4][4], bf[4][2];
            #pragma unroll
            for (int mi = 0; mi < 4; mi++) {
                int r = wm + mi * 16 + grp;
                af[mi][0] = __float_as_uint(as[(r    ) * (BK + AP) + kb + qd    ]);
                af[mi][1] = __float_as_uint(as[(r + 8) * (BK + AP) + kb + qd    ]);
                af[mi][2] = __float_as_uint(as[(r    ) * (BK + AP) + kb + qd + 4]);
                af[mi][3] = __float_as_uint(as[(r + 8) * (BK + AP) + kb + qd + 4]);
            }
            #pragma unroll
            for (int ni = 0; ni < 4; ni++) {
                int c = wn + ni * 8 + grp;
                if (TRANSB) {
                    bf[ni][0] = __float_as_uint(bs[c * (BK + AP) + kb + qd    ]);
                    bf[ni][1] = __float_as_uint(bs[c * (BK + AP) + kb + qd + 4]);
                } else {
                    bf[ni][0] = __float_as_uint(bs[(kb + qd    ) * (BN + 8) + c]);
                    bf[ni][1] = __float_as_uint(bs[(kb + qd + 4) * (BN + 8) + c]);
                }
            }
            #pragma unroll
            for (int mi = 0; mi < 4; mi++)
                #pragma unroll
                for (int ni = 0; ni < 4; ni++)
                    mma_tf32(acc[mi][ni], af[mi][0], af[mi][1], af[mi][2], af[mi][3],
                             bf[ni][0], bf[ni][1]);
        }
    };

    const int NC = K / BK;
    load_tiles(0, 0);
    for (int c = 0; c < NC; c++) {
        if (c + 1 < NC) {
            load_tiles((c + 1) * BK, (c + 1) & 1);
            asm volatile("cp.async.wait_group 1;\n");
        } else {
            asm volatile("cp.async.wait_group 0;\n");
        }
        __syncthreads();
        compute(c & 1);
        __syncthreads();
    }

    #pragma unroll
    for (int mi = 0; mi < 4; mi++) {
        int r = bm + wm + mi * 16 + grp;
        #pragma unroll
        for (int ni = 0; ni < 4; ni++) {
            int cl = bn + wn + ni * 8 + 2 * qd;
            float bb0 = 0.f, bb1 = 0.f;
            if (HAS_BIAS) { bb0 = bias[cl]; bb1 = bias[cl + 1]; }
            float2 v0 = { acc[mi][ni][0] * alpha + bb0, acc[mi][ni][1] * alpha + bb1 };
            float2 v1 = { acc[mi][ni][2] * alpha + bb0, acc[mi][ni][3] * alpha + bb1 };
            *reinterpret_cast<float2*>(&C[(size_t)(r    ) * ldc + cl]) = v0;
            *reinterpret_cast<float2*>(&C[(size_t)(r + 8) * ldc + cl]) = v1;
        }
    }
}

// ---------------- row softmax (rounds P to tf32 on store) -------------------
__global__ __launch_bounds__(256)
void softmax_kernel() {
    const size_t row = blockIdx.x;
    float* p = g_S + row * (size_t)T_;
    const int tid = threadIdx.x;

    float v[8];
    float mx = -INFINITY;
    #pragma unroll
    for (int i = 0; i < 8; i++) {
        v[i] = p[tid + i * 256];
        mx = fmaxf(mx, v[i]);
    }
    __shared__ float red[8];
    #pragma unroll
    for (int o = 16; o > 0; o >>= 1) mx = fmaxf(mx, __shfl_xor_sync(~0u, mx, o));
    if ((tid & 31) == 0) red[tid >> 5] = mx;
    __syncthreads();
    mx = fmaxf(fmaxf(fmaxf(red[0], red[1]), fmaxf(red[2], red[3])),
               fmaxf(fmaxf(red[4], red[5]), fmaxf(red[6], red[7])));
    __syncthreads();

    float sum = 0.f;
    #pragma unroll
    for (int i = 0; i < 8; i++) {
        v[i] = __expf(v[i] - mx);
        sum += v[i];
    }
    #pragma unroll
    for (int o = 16; o > 0; o >>= 1) sum += __shfl_xor_sync(~0u, sum, o);
    if ((tid & 31) == 0) red[tid >> 5] = sum;
    __syncthreads();
    sum = red[0] + red[1] + red[2] + red[3] + red[4] + red[5] + red[6] + red[7];

    const float inv = 1.f / sum;
    #pragma unroll
    for (int i = 0; i < 8; i++) p[tid + i * 256] = tf32r(v[i] * inv);
}

// ---------------- merge heads: [b,h,t,d] -> [b,t,h*d] (rounded) -------------
__global__ __launch_bounds__(256)
void merge_heads_kernel() {
    int idx = blockIdx.x * blockDim.x + threadIdx.x;
    int d = idx & 63;
    int h = (idx >> 6) & 15;
    int t = (idx >> 10) & 2047;
    int b = idx >> 21;
    g_ctx[idx] = tf32r(g_pv[((size_t)(b * H_ + h) * T_ + t) * HD_ + d]);
}

// ---------------- launch ----------------------------------------------------
extern "C" void kernel_launch(void* const* d_in, const int* in_sizes, int n_in,
                              void* d_out, int out_size)
{
    const float* x      = (const float*)d_in[0];
    const float* W_attn = (const float*)d_in[1];
    const float* b_attn = (const float*)d_in[2];
    const float* W_proj = (const float*)d_in[3];
    const float* b_proj = (const float*)d_in[4];
    float* out = (float*)d_out;

    float *qkv, *q, *k, *v, *pv, *ctx, *S, *xr, *war, *wpr;
    cudaGetSymbolAddress((void**)&qkv, g_qkv);
    cudaGetSymbolAddress((void**)&q,   g_q);
    cudaGetSymbolAddress((void**)&k,   g_k);
    cudaGetSymbolAddress((void**)&v,   g_v);
    cudaGetSymbolAddress((void**)&pv,  g_pv);
    cudaGetSymbolAddress((void**)&ctx, g_ctx);
    cudaGetSymbolAddress((void**)&S,   g_S);
    cudaGetSymbolAddress((void**)&xr,  g_xr);
    cudaGetSymbolAddress((void**)&war, g_war);
    cudaGetSymbolAddress((void**)&wpr, g_wpr);

    // smem sizes per instantiation
    const int SM_BIG_NT = (128 * 36 + 32 * 136) * 2 * 4;   // 71680 (QKV, proj)
    const int SM_BIG_TB = (128 * 36 + 128 * 36) * 2 * 4;   // 73728 (scores)
    const int SM_PV     = (128 * 36 + 32 * 72) * 2 * 4;    // 55296 (PV)

    cudaFuncSetAttribute((const void*)tgemm<128,128,256,false,true>,
                         cudaFuncAttributeMaxDynamicSharedMemorySize, SM_BIG_NT);
    cudaFuncSetAttribute((const void*)tgemm<128,128,256,true,false>,
                         cudaFuncAttributeMaxDynamicSharedMemorySize, SM_BIG_TB);
    cudaFuncSetAttribute((const void*)tgemm<128,64,128,false,false>,
                         cudaFuncAttributeMaxDynamicSharedMemorySize, SM_PV);
    cudaFuncSetAttribute((const void*)tgemm<128,128,256,false,false>,
                         cudaFuncAttributeMaxDynamicSharedMemorySize, SM_BIG_NT);

    // 0. tf32-rounded copies of GEMM inputs
    round_copy_kernel<<<(BT * D_ / 4 + 255) / 256, 256>>>((const float4*)x,  (float4*)xr,  BT * D_ / 4);
    round_copy_kernel<<<(D_ * 3 * D_ / 4 + 255) / 256, 256>>>((const float4*)W_attn, (float4*)war, D_ * 3 * D_ / 4);
    round_copy_kernel<<<(D_ * D_ / 4 + 255) / 256, 256>>>((const float4*)W_proj, (float4*)wpr, D_ * D_ / 4);

    // 1. RoPE tables
    rope_tables_kernel<<<(T_ * 32) / 256, 256>>>();

    // 2. QKV GEMM: [8192,1024] @ [1024,3072] + b_attn
    {
        dim3 grid(3 * D_ / 128, BT / 128, 1);
        tgemm<128,128,256,false,true><<<grid, 256, SM_BIG_NT>>>(
            xr, war, b_attn, qkv, D_, D_, 3 * D_, 3 * D_, 0, 0, 0, 1.0f);
    }

    // 3. split heads + RoPE
    rope_apply_kernel<<<(B_ * T_ * H_ * 32) / 256, 256>>>();

    // 4. scores: S[z] = q[z] @ k[z]^T / sqrt(512)
    {
        dim3 grid(T_ / 128, T_ / 128, BH);
        tgemm<128,128,256,true,false><<<grid, 256, SM_BIG_TB>>>(
            q, k, nullptr, S, HD_, HD_, HD_, T_,
            (long)T_ * HD_, (long)T_ * HD_, (long)T_ * T_,
            0.044194173824159216f);
    }

    // 5. softmax rows
    softmax_kernel<<<BH * T_, 256>>>();

    // 6. PV: O[z] = P[z] @ V[z]
    {
        dim3 grid(HD_ / 64, T_ / 128, BH);
        tgemm<128,64,128,false,false><<<grid, 128, SM_PV>>>(
            S, v, nullptr, pv, T_, T_, HD_, HD_,
            (long)T_ * T_, (long)T_ * HD_, (long)T_ * HD_, 1.0f);
    }

    // 7. merge heads
    merge_heads_kernel<<<(BT * D_) / 256, 256>>>();

    // 8. output projection
    {
        dim3 grid(D_ / 128, BT / 128, 1);
        tgemm<128,128,256,false,true><<<grid, 256, SM_BIG_NT>>>(
            ctx, wpr, b_proj, out, D_, D_, D_, D_, 0, 0, 0, 1.0f);
    }
}

// round 3
// speedup vs baseline: 3.4171x; 1.4303x over previous
#include <cuda_runtime.h>
#include <cuda_bf16.h>
#include <math.h>
#include <stdint.h>

// Problem constants
#define B_  4
#define T_  2048
#define D_  1024
#define H_  16
#define HD_ 64
#define BT  (B_ * T_)            // 8192
#define BH  (B_ * H_)            // 64

#define SCALE 0.044194173824159216f   // 1/sqrt(512)

// ---------------- scratch (device globals; no allocation allowed) ----------
__device__ float g_qkv[(size_t)BT * (3 * D_)];
__device__ float g_q  [(size_t)BH * T_ * HD_];
__device__ float g_k  [(size_t)BH * T_ * HD_];
__device__ float g_v  [(size_t)BH * T_ * HD_];
__device__ float g_ctx[(size_t)BT * D_];
__device__ float g_sin[T_ * (HD_ / 2)];
__device__ float g_cos[T_ * (HD_ / 2)];
__device__ float g_xr [(size_t)BT * D_];
__device__ float g_war[(size_t)D_ * 3 * D_];
__device__ float g_wpr[(size_t)D_ * D_];

// ---------------- helpers ----------------------------------------------------
__device__ __forceinline__ float tf32r(float x) {
    float y;
    asm("cvt.rna.tf32.f32 %0, %1;" : "=f"(y) : "f"(x));
    return y;
}

__device__ __forceinline__ void cp_async16(void* smem, const void* gmem) {
    uint32_t s = (uint32_t)__cvta_generic_to_shared(smem);
    asm volatile("cp.async.cg.shared.global [%0], [%1], 16;\n" :: "r"(s), "l"(gmem));
}

__device__ __forceinline__ void mma_tf32(float c[4],
    uint32_t a0, uint32_t a1, uint32_t a2, uint32_t a3,
    uint32_t b0, uint32_t b1)
{
    asm volatile(
        "mma.sync.aligned.m16n8k8.row.col.f32.tf32.tf32.f32 "
        "{%0,%1,%2,%3}, {%4,%5,%6,%7}, {%8,%9}, {%0,%1,%2,%3};\n"
        : "+f"(c[0]), "+f"(c[1]), "+f"(c[2]), "+f"(c[3])
        : "r"(a0), "r"(a1), "r"(a2), "r"(a3), "r"(b0), "r"(b1));
}

// ---------------- RoPE tables -----------------------------------------------
__global__ void rope_tables_kernel() {
    int idx = blockIdx.x * blockDim.x + threadIdx.x;
    if (idx >= T_ * (HD_ / 2)) return;
    int j = idx & 31;
    int t = idx >> 5;
    double theta = pow(1000.0, -2.0 * (double)(j + 1) / (double)HD_);
    double ang = (double)(t + 1) * theta;
    g_sin[idx] = (float)sin(ang);
    g_cos[idx] = (float)cos(ang);
}

// ---------------- tf32-round copy -------------------------------------------
__global__ void round_copy_kernel(const float4* __restrict__ src,
                                  float4* __restrict__ dst, int n4) {
    int i = blockIdx.x * blockDim.x + threadIdx.x;
    if (i >= n4) return;
    float4 v = src[i];
    v.x = tf32r(v.x); v.y = tf32r(v.y); v.z = tf32r(v.z); v.w = tf32r(v.w);
    dst[i] = v;
}

// ---------------- split heads + RoPE (q pre-scaled, tf32-rounded) -----------
__global__ void rope_apply_kernel() {
    int idx = blockIdx.x * blockDim.x + threadIdx.x;
    int j = idx & 31;
    int h = (idx >> 5) & 15;
    int t = (idx >> 9) & 2047;
    int b = idx >> 20;
    size_t base = (size_t)(b * T_ + t) * (3 * D_);
    int c = h * HD_ + 2 * j;
    float q0 = g_qkv[base + c],            q1 = g_qkv[base + c + 1];
    float k0 = g_qkv[base + D_ + c],       k1 = g_qkv[base + D_ + c + 1];
    float v0 = g_qkv[base + 2 * D_ + c],   v1 = g_qkv[base + 2 * D_ + c + 1];
    float sn = g_sin[t * 32 + j];
    float cs = g_cos[t * 32 + j];
    size_t o = ((size_t)(b * H_ + h) * T_ + t) * HD_ + 2 * j;
    g_q[o]     = tf32r((q0 * cs - q1 * sn) * SCALE);
    g_q[o + 1] = tf32r((q1 * cs + q0 * sn) * SCALE);
    g_k[o]     = tf32r(k0 * cs - k1 * sn);
    g_k[o + 1] = tf32r(k1 * cs + k0 * sn);
    g_v[o]     = tf32r(v0);
    g_v[o + 1] = tf32r(v1);
}

// ---------------- TF32 tensor-core GEMM (QKV + proj) -------------------------
template<int BM, int BN, int THREADS, bool TRANSB, bool HAS_BIAS>
__global__ __launch_bounds__(THREADS)
void tgemm(const float* __restrict__ A, const float* __restrict__ Bm,
           const float* __restrict__ bias, float* __restrict__ C,
           int K, int lda, int ldb, int ldc,
           long sA, long sB, long sC, float alpha)
{
    constexpr int BK = 32;
    constexpr int WM = 64, WN = 32;
    constexpr int WARPS_M = BM / WM;
    constexpr int WARPS_N = BN / WN;
    static_assert(WARPS_M * WARPS_N * 32 == THREADS, "thread count");
    constexpr int AP = 4;
    constexpr int A_SZ = BM * (BK + AP);
    constexpr int B_SZ = TRANSB ? BN * (BK + AP) : BK * (BN + 8);
    constexpr int STG = A_SZ + B_SZ;

    extern __shared__ float sm[];

    const int z = blockIdx.z;
    A  += (size_t)z * sA;
    Bm += (size_t)z * sB;
    C  += (size_t)z * sC;
    const int bm = blockIdx.y * BM;
    const int bn = blockIdx.x * BN;

    const int tid  = threadIdx.x;
    const int warp = tid >> 5;
    const int lane = tid & 31;
    const int grp  = lane >> 2;
    const int qd   = lane & 3;
    const int wm   = (warp % WARPS_M) * WM;
    const int wn   = (warp / WARPS_M) * WN;

    float acc[4][4][4];
    #pragma unroll
    for (int i = 0; i < 4; i++)
        #pragma unroll
        for (int j = 0; j < 4; j++)
            #pragma unroll
            for (int r = 0; r < 4; r++) acc[i][j][r] = 0.f;

    auto load_tiles = [&](int k0, int s) {
        float* as = sm + s * STG;
        float* bs = as + A_SZ;
        constexpr int A_IT = (BM * 8) / THREADS;
        #pragma unroll
        for (int i = 0; i < A_IT; i++) {
            int v  = tid + i * THREADS;
            int m  = v >> 3;
            int kq = (v & 7) * 4;
            cp_async16(&as[m * (BK + AP) + kq],
                       &A[(size_t)(bm + m) * lda + k0 + kq]);
        }
        if (TRANSB) {
            constexpr int B_IT = (BN * 8) / THREADS;
            #pragma unroll
            for (int i = 0; i < B_IT; i++) {
                int v  = tid + i * THREADS;
                int n  = v >> 3;
                int kq = (v & 7) * 4;
                cp_async16(&bs[n * (BK + AP) + kq],
                           &Bm[(size_t)(bn + n) * ldb + k0 + kq]);
            }
        } else {
            constexpr int B_IT = (BK * (BN / 4)) / THREADS;
            #pragma unroll
            for (int i = 0; i < B_IT; i++) {
                int v  = tid + i * THREADS;
                int k  = v / (BN / 4);
                int n4 = (v % (BN / 4)) * 4;
                cp_async16(&bs[k * (BN + 8) + n4],
                           &Bm[(size_t)(k0 + k) * ldb + bn + n4]);
            }
        }
        asm volatile("cp.async.commit_group;\n");
    };

    auto compute = [&](int s) {
        const float* as = sm + s * STG;
        const float* bs = as + A_SZ;
        #pragma unroll
        for (int ks = 0; ks < 4; ks++) {
            const int kb = ks * 8;
            uint32_t af[4][4], bf[4][2];
            #pragma unroll
            for (int mi = 0; mi < 4; mi++) {
                int r = wm + mi * 16 + grp;
                af[mi][0] = __float_as_uint(as[(r    ) * (BK + AP) + kb + qd    ]);
                af[mi][1] = __float_as_uint(as[(r + 8) * (BK + AP) + kb + qd    ]);
                af[mi][2] = __float_as_uint(as[(r    ) * (BK + AP) + kb + qd + 4]);
                af[mi][3] = __float_as_uint(as[(r + 8) * (BK + AP) + kb + qd + 4]);
            }
            #pragma unroll
            for (int ni = 0; ni < 4; ni++) {
                int c = wn + ni * 8 + grp;
                if (TRANSB) {
                    bf[ni][0] = __float_as_uint(bs[c * (BK + AP) + kb + qd    ]);
                    bf[ni][1] = __float_as_uint(bs[c * (BK + AP) + kb + qd + 4]);
                } else {
                    bf[ni][0] = __float_as_uint(bs[(kb + qd    ) * (BN + 8) + c]);
                    bf[ni][1] = __float_as_uint(bs[(kb + qd + 4) * (BN + 8) + c]);
                }
            }
            #pragma unroll
            for (int mi = 0; mi < 4; mi++)
                #pragma unroll
                for (int ni = 0; ni < 4; ni++)
                    mma_tf32(acc[mi][ni], af[mi][0], af[mi][1], af[mi][2], af[mi][3],
                             bf[ni][0], bf[ni][1]);
        }
    };

    const int NC = K / BK;
    load_tiles(0, 0);
    for (int c = 0; c < NC; c++) {
        if (c + 1 < NC) {
            load_tiles((c + 1) * BK, (c + 1) & 1);
            asm volatile("cp.async.wait_group 1;\n");
        } else {
            asm volatile("cp.async.wait_group 0;\n");
        }
        __syncthreads();
        compute(c & 1);
        __syncthreads();
    }

    #pragma unroll
    for (int mi = 0; mi < 4; mi++) {
        int r = bm + wm + mi * 16 + grp;
        #pragma unroll
        for (int ni = 0; ni < 4; ni++) {
            int cl = bn + wn + ni * 8 + 2 * qd;
            float bb0 = 0.f, bb1 = 0.f;
            if (HAS_BIAS) { bb0 = bias[cl]; bb1 = bias[cl + 1]; }
            float2 v0 = { acc[mi][ni][0] * alpha + bb0, acc[mi][ni][1] * alpha + bb1 };
            float2 v1 = { acc[mi][ni][2] * alpha + bb0, acc[mi][ni][3] * alpha + bb1 };
            *reinterpret_cast<float2*>(&C[(size_t)(r    ) * ldc + cl]) = v0;
            *reinterpret_cast<float2*>(&C[(size_t)(r + 8) * ldc + cl]) = v1;
        }
    }
}

// ---------------- fused flash attention --------------------------------------
// Grid: (T_/128, BH). 256 threads = 8 warps. Each warp: 16 Q rows x full KV.
// smem floats: Ks[2][128*68], Vs[2][128*72], P/Qstage[8][16*132]
#define KS_STR 68
#define VS_STR 72
#define PS_STR 132
#define FL_KS0 0
#define FL_KS1 (128 * KS_STR)
#define FL_VS0 (2 * 128 * KS_STR)
#define FL_VS1 (FL_VS0 + 128 * VS_STR)
#define FL_PS  (FL_VS0 + 2 * 128 * VS_STR)
#define FL_SMEM_FLOATS (FL_PS + 8 * 16 * PS_STR)
#define FL_SMEM_BYTES (FL_SMEM_FLOATS * 4)   // 210944

__global__ __launch_bounds__(256, 1)
void flash_kernel()
{
    extern __shared__ float sm[];
    const int z  = blockIdx.y;              // b*H + h
    const int qt = blockIdx.x;              // q tile index
    const int b  = z >> 4;
    const int h  = z & 15;
    const float* Q = g_q + (size_t)z * T_ * HD_ + (size_t)qt * 128 * HD_;
    const float* K = g_k + (size_t)z * T_ * HD_;
    const float* V = g_v + (size_t)z * T_ * HD_;

    const int tid  = threadIdx.x;
    const int warp = tid >> 5;
    const int lane = tid & 31;
    const int grp  = lane >> 2;
    const int qd   = lane & 3;

    float* Pw = sm + FL_PS + warp * (16 * PS_STR);

    // ---- stage Q through the P region, load frags to registers ----
    {
        float* Qs = sm + FL_PS;             // stride 68
        #pragma unroll
        for (int i = 0; i < 8; i++) {
            int v4 = tid + i * 256;         // 0..2047
            int r  = v4 >> 4;
            int c  = (v4 & 15) * 4;
            cp_async16(&Qs[r * KS_STR + c], &Q[r * HD_ + c]);
        }
        asm volatile("cp.async.commit_group;\ncp.async.wait_group 0;\n");
        __syncthreads();
    }
    uint32_t qf[8][4];
    {
        const float* Qs = sm + FL_PS;
        const int r0 = warp * 16 + grp;
        #pragma unroll
        for (int ks = 0; ks < 8; ks++) {
            qf[ks][0] = __float_as_uint(Qs[(r0    ) * KS_STR + ks * 8 + qd    ]);
            qf[ks][1] = __float_as_uint(Qs[(r0 + 8) * KS_STR + ks * 8 + qd    ]);
            qf[ks][2] = __float_as_uint(Qs[(r0    ) * KS_STR + ks * 8 + qd + 4]);
            qf[ks][3] = __float_as_uint(Qs[(r0 + 8) * KS_STR + ks * 8 + qd + 4]);
        }
    }
    __syncthreads();                        // P region free again

    auto load_kv = [&](int kv0, int buf) {
        float* ks = sm + (buf ? FL_KS1 : FL_KS0);
        float* vs = sm + (buf ? FL_VS1 : FL_VS0);
        #pragma unroll
        for (int i = 0; i < 8; i++) {
            int v4 = tid + i * 256;
            int r  = v4 >> 4;
            int c  = (v4 & 15) * 4;
            cp_async16(&ks[r * KS_STR + c], &K[(size_t)(kv0 + r) * HD_ + c]);
        }
        #pragma unroll
        for (int i = 0; i < 8; i++) {
            int v4 = tid + i * 256;
            int r  = v4 >> 4;
            int c  = (v4 & 15) * 4;
            cp_async16(&vs[r * VS_STR + c], &V[(size_t)(kv0 + r) * HD_ + c]);
        }
        asm volatile("cp.async.commit_group;\n");
    };

    load_kv(0, 0);

    float m0 = -INFINITY, m1 = -INFINITY;
    float l0 = 0.f, l1 = 0.f;
    float o[8][4];
    #pragma unroll
    for (int ni = 0; ni < 8; ni++)
        #pragma unroll
        for (int r = 0; r < 4; r++) o[ni][r] = 0.f;

    const int NIT = T_ / 128;               // 16
    for (int it = 0; it < NIT; it++) {
        const int buf = it & 1;
        asm volatile("cp.async.wait_group 0;\n");
        __syncthreads();
        if (it + 1 < NIT) load_kv((it + 1) * 128, buf ^ 1);

        const float* ks = sm + (buf ? FL_KS1 : FL_KS0);
        const float* vs = sm + (buf ? FL_VS1 : FL_VS0);

        // ---- S = Q @ K^T (16 n-tiles of width 8) ----
        float sacc[16][4];
        #pragma unroll
        for (int ni = 0; ni < 16; ni++)
            #pragma unroll
            for (int r = 0; r < 4; r++) sacc[ni][r] = 0.f;

        #pragma unroll
        for (int kst = 0; kst < 8; kst++) {
            const int kb = kst * 8;
            #pragma unroll
            for (int ni = 0; ni < 16; ni++) {
                uint32_t b0 = __float_as_uint(ks[(ni * 8 + grp) * KS_STR + kb + qd    ]);
                uint32_t b1 = __float_as_uint(ks[(ni * 8 + grp) * KS_STR + kb + qd + 4]);
                mma_tf32(sacc[ni], qf[kst][0], qf[kst][1], qf[kst][2], qf[kst][3], b0, b1);
            }
        }

        // ---- online softmax (rows grp and grp+8, intra-quad reduce) ----
        float xm0 = -INFINITY, xm1 = -INFINITY;
        #pragma unroll
        for (int ni = 0; ni < 16; ni++) {
            xm0 = fmaxf(xm0, fmaxf(sacc[ni][0], sacc[ni][1]));
            xm1 = fmaxf(xm1, fmaxf(sacc[ni][2], sacc[ni][3]));
        }
        xm0 = fmaxf(xm0, __shfl_xor_sync(~0u, xm0, 1));
        xm0 = fmaxf(xm0, __shfl_xor_sync(~0u, xm0, 2));
        xm1 = fmaxf(xm1, __shfl_xor_sync(~0u, xm1, 1));
        xm1 = fmaxf(xm1, __shfl_xor_sync(~0u, xm1, 2));

        const float nm0 = fmaxf(m0, xm0);
        const float nm1 = fmaxf(m1, xm1);
        const float f0 = __expf(m0 - nm0);
        const float f1 = __expf(m1 - nm1);
        m0 = nm0; m1 = nm1;

        float s0 = 0.f, s1 = 0.f;
        #pragma unroll
        for (int ni = 0; ni < 16; ni++) {
            float e0 = __expf(sacc[ni][0] - nm0);
            float e1 = __expf(sacc[ni][1] - nm0);
            float e2 = __expf(sacc[ni][2] - nm1);
            float e3 = __expf(sacc[ni][3] - nm1);
            s0 += e0 + e1;
            s1 += e2 + e3;
            float2* p0 = reinterpret_cast<float2*>(&Pw[(grp    ) * PS_STR + ni * 8 + 2 * qd]);
            float2* p1 = reinterpret_cast<float2*>(&Pw[(grp + 8) * PS_STR + ni * 8 + 2 * qd]);
            *p0 = make_float2(tf32r(e0), tf32r(e1));
            *p1 = make_float2(tf32r(e2), tf32r(e3));
        }
        s0 += __shfl_xor_sync(~0u, s0, 1);
        s0 += __shfl_xor_sync(~0u, s0, 2);
        s1 += __shfl_xor_sync(~0u, s1, 1);
        s1 += __shfl_xor_sync(~0u, s1, 2);
        l0 = l0 * f0 + s0;
        l1 = l1 * f1 + s1;

        #pragma unroll
        for (int ni = 0; ni < 8; ni++) {
            o[ni][0] *= f0; o[ni][1] *= f0;
            o[ni][2] *= f1; o[ni][3] *= f1;
        }
        __syncwarp();

        // ---- O += P @ V (16 k-steps over kv, 8 n-tiles over hd) ----
        #pragma unroll
        for (int kst = 0; kst < 16; kst++) {
            const int kb = kst * 8;
            uint32_t a0 = __float_as_uint(Pw[(grp    ) * PS_STR + kb + qd    ]);
            uint32_t a1 = __float_as_uint(Pw[(grp + 8) * PS_STR + kb + qd    ]);
            uint32_t a2 = __float_as_uint(Pw[(grp    ) * PS_STR + kb + qd + 4]);
            uint32_t a3 = __float_as_uint(Pw[(grp + 8) * PS_STR + kb + qd + 4]);
            #pragma unroll
            for (int ni = 0; ni < 8; ni++) {
                uint32_t b0 = __float_as_uint(vs[(kb + qd    ) * VS_STR + ni * 8 + grp]);
                uint32_t b1 = __float_as_uint(vs[(kb + qd + 4) * VS_STR + ni * 8 + grp]);
                mma_tf32(o[ni], a0, a1, a2, a3, b0, b1);
            }
        }
    }

    // ---- normalize + fused merge_heads write (tf32-rounded for proj) ----
    const float i0 = 1.f / l0;
    const float i1 = 1.f / l1;
    const int t0 = qt * 128 + warp * 16 + grp;
    #pragma unroll
    for (int ni = 0; ni < 8; ni++) {
        int col = h * HD_ + ni * 8 + 2 * qd;
        float2 v0 = make_float2(tf32r(o[ni][0] * i0), tf32r(o[ni][1] * i0));
        float2 v1 = make_float2(tf32r(o[ni][2] * i1), tf32r(o[ni][3] * i1));
        *reinterpret_cast<float2*>(&g_ctx[(size_t)(b * T_ + t0    ) * D_ + col]) = v0;
        *reinterpret_cast<float2*>(&g_ctx[(size_t)(b * T_ + t0 + 8) * D_ + col]) = v1;
    }
}

// ---------------- launch ----------------------------------------------------
extern "C" void kernel_launch(void* const* d_in, const int* in_sizes, int n_in,
                              void* d_out, int out_size)
{
    const float* x      = (const float*)d_in[0];
    const float* W_attn = (const float*)d_in[1];
    const float* b_attn = (const float*)d_in[2];
    const float* W_proj = (const float*)d_in[3];
    const float* b_proj = (const float*)d_in[4];
    float* out = (float*)d_out;

    float *qkv, *ctx, *xr, *war, *wpr;
    cudaGetSymbolAddress((void**)&qkv, g_qkv);
    cudaGetSymbolAddress((void**)&ctx, g_ctx);
    cudaGetSymbolAddress((void**)&xr,  g_xr);
    cudaGetSymbolAddress((void**)&war, g_war);
    cudaGetSymbolAddress((void**)&wpr, g_wpr);

    const int SM_BIG_NT = (128 * 36 + 32 * 136) * 2 * 4;   // 71680

    cudaFuncSetAttribute((const void*)tgemm<128,128,256,false,true>,
                         cudaFuncAttributeMaxDynamicSharedMemorySize, SM_BIG_NT);
    cudaFuncSetAttribute((const void*)flash_kernel,
                         cudaFuncAttributeMaxDynamicSharedMemorySize, FL_SMEM_BYTES);

    // 0. tf32-rounded copies of GEMM inputs
    round_copy_kernel<<<(BT * D_ / 4 + 255) / 256, 256>>>((const float4*)x,  (float4*)xr,  BT * D_ / 4);
    round_copy_kernel<<<(D_ * 3 * D_ / 4 + 255) / 256, 256>>>((const float4*)W_attn, (float4*)war, D_ * 3 * D_ / 4);
    round_copy_kernel<<<(D_ * D_ / 4 + 255) / 256, 256>>>((const float4*)W_proj, (float4*)wpr, D_ * D_ / 4);

    // 1. RoPE tables
    rope_tables_kernel<<<(T_ * 32) / 256, 256>>>();

    // 2. QKV GEMM: [8192,1024] @ [1024,3072] + b_attn
    {
        dim3 grid(3 * D_ / 128, BT / 128, 1);
        tgemm<128,128,256,false,true><<<grid, 256, SM_BIG_NT>>>(
            xr, war, b_attn, qkv, D_, D_, 3 * D_, 3 * D_, 0, 0, 0, 1.0f);
    }

    // 3. split heads + RoPE (q pre-scaled by 1/sqrt(512))
    rope_apply_kernel<<<(B_ * T_ * H_ * 32) / 256, 256>>>();

    // 4-7. fused flash attention (writes merged ctx directly)
    {
        dim3 grid(T_ / 128, BH);
        flash_kernel<<<grid, 256, FL_SMEM_BYTES>>>();
    }

    // 8. output projection
    {
        dim3 grid(D_ / 128, BT / 128, 1);
        tgemm<128,128,256,false,true><<<grid, 256, SM_BIG_NT>>>(
            ctx, wpr, b_proj, out, D_, D_, D_, D_, 0, 0, 0, 1.0f);
    }
}

// round 5
// speedup vs baseline: 6.4293x; 1.8815x over previous
#include <cuda_runtime.h>
#include <cuda_fp16.h>
#include <math.h>
#include <stdint.h>

// Problem constants
#define B_  4
#define T_  2048
#define D_  1024
#define H_  16
#define HD_ 64
#define BT  (B_ * T_)            // 8192
#define BH  (B_ * H_)            // 64

#define SCALE 0.044194173824159216f   // 1/sqrt(512)

// ---------------- scratch (device globals; no allocation allowed) ----------
__device__ float  g_qkv[(size_t)BT * (3 * D_)];       // f32 QKV GEMM output
__device__ __half g_xh [(size_t)BT * D_];             // x in fp16
__device__ __half g_wah[(size_t)(3 * D_) * D_];       // W_attn^T [3072][1024] fp16
__device__ __half g_wph[(size_t)D_ * D_];             // W_proj^T [1024][1024] fp16
__device__ __half g_q  [(size_t)BH * T_ * HD_];       // [z][t][hd], pre-scaled
__device__ __half g_k  [(size_t)BH * T_ * HD_];       // [z][t][hd]
__device__ __half g_vt [(size_t)BH * HD_ * T_];       // [z][hd][t]  (transposed!)
__device__ __half g_ctx[(size_t)BT * D_];             // merged heads fp16
__device__ float  g_sin[T_ * 32];
__device__ float  g_cos[T_ * 32];

// ---------------- helpers ----------------------------------------------------
__device__ __forceinline__ void cp_async16(void* smem, const void* gmem) {
    uint32_t s = (uint32_t)__cvta_generic_to_shared(smem);
    asm volatile("cp.async.cg.shared.global [%0], [%1], 16;\n" :: "r"(s), "l"(gmem));
}

__device__ __forceinline__ void mma_fp16(float c[4],
    uint32_t a0, uint32_t a1, uint32_t a2, uint32_t a3,
    uint32_t b0, uint32_t b1)
{
    asm volatile(
        "mma.sync.aligned.m16n8k16.row.col.f32.f16.f16.f32 "
        "{%0,%1,%2,%3}, {%4,%5,%6,%7}, {%8,%9}, {%0,%1,%2,%3};\n"
        : "+f"(c[0]), "+f"(c[1]), "+f"(c[2]), "+f"(c[3])
        : "r"(a0), "r"(a1), "r"(a2), "r"(a3), "r"(b0), "r"(b1));
}

__device__ __forceinline__ uint32_t h2u(__half2 h) {
    return *reinterpret_cast<uint32_t*>(&h);
}

// ---------------- RoPE tables (double arg-reduction + MUFU) ------------------
__global__ void rope_tables_kernel() {
    __shared__ double th[32];
    if (threadIdx.x < 32)
        th[threadIdx.x] = pow(1000.0, -2.0 * (double)(threadIdx.x + 1) / 64.0);
    __syncthreads();
    int idx = blockIdx.x * 256 + threadIdx.x;   // t*32 + j
    int j = idx & 31;
    int t = idx >> 5;
    const double TWO_PI = 6.283185307179586476925286766559;
    double ang = (double)(t + 1) * th[j];
    double red = ang - floor(ang * (1.0 / TWO_PI)) * TWO_PI;
    float a = (float)red;
    g_sin[idx] = __sinf(a);
    g_cos[idx] = __cosf(a);
}

// ---------------- f32 -> f16 copy (x) ----------------------------------------
__global__ void f2h_kernel(const float4* __restrict__ src,
                           uint2* __restrict__ dst, int n4) {
    int i = blockIdx.x * blockDim.x + threadIdx.x;
    if (i >= n4) return;
    float4 v = src[i];
    __half2 h0 = __floats2half2_rn(v.x, v.y);
    __half2 h1 = __floats2half2_rn(v.z, v.w);
    dst[i] = make_uint2(h2u(h0), h2u(h1));
}

// ---------------- transpose + f16 (weights): src f32 [K][N] -> dst f16 [N][K]
__global__ void transpose_h_kernel(const float* __restrict__ src,
                                   __half* __restrict__ dst, int K, int N) {
    __shared__ float tile[32][33];
    int n0 = blockIdx.x * 32, k0 = blockIdx.y * 32;
    int tx = threadIdx.x, ty = threadIdx.y;   // 32 x 8
    #pragma unroll
    for (int i = 0; i < 32; i += 8)
        tile[ty + i][tx] = src[(size_t)(k0 + ty + i) * N + n0 + tx];
    __syncthreads();
    #pragma unroll
    for (int i = 0; i < 32; i += 8)
        dst[(size_t)(n0 + ty + i) * K + k0 + tx] = __float2half_rn(tile[tx][ty + i]);
}

// ---------------- split heads + RoPE + V transpose ---------------------------
// grid (T_/128, BH), block 256. Writes q,k [z][t][hd] and v [z][hd][t].
#define VR_STR 133
__global__ __launch_bounds__(256)
void rope_apply_kernel() {
    __shared__ float vsm[64 * VR_STR];
    const int z  = blockIdx.y;
    const int b  = z >> 4;
    const int h  = z & 15;
    const int t0 = blockIdx.x * 128;
    const int tid = threadIdx.x;

    #pragma unroll
    for (int i = 0; i < 16; i++) {
        int idx = tid + i * 256;            // 0..4095: (tl, j)
        int tl = idx >> 5;
        int j  = idx & 31;
        size_t base = (size_t)(b * T_ + t0 + tl) * (3 * D_);
        int c = h * HD_ + 2 * j;
        float2 qv = *(const float2*)&g_qkv[base + c];
        float2 kv = *(const float2*)&g_qkv[base + D_ + c];
        float2 vv = *(const float2*)&g_qkv[base + 2 * D_ + c];
        float sn = g_sin[(t0 + tl) * 32 + j];
        float cs = g_cos[(t0 + tl) * 32 + j];
        __half2 qh = __floats2half2_rn((qv.x * cs - qv.y * sn) * SCALE,
                                       (qv.y * cs + qv.x * sn) * SCALE);
        __half2 kh = __floats2half2_rn(kv.x * cs - kv.y * sn,
                                       kv.y * cs + kv.x * sn);
        size_t o = ((size_t)z * T_ + t0 + tl) * HD_ + 2 * j;
        *reinterpret_cast<uint32_t*>(&g_q[o]) = h2u(qh);
        *reinterpret_cast<uint32_t*>(&g_k[o]) = h2u(kh);
        vsm[(2 * j    ) * VR_STR + tl] = vv.x;
        vsm[(2 * j + 1) * VR_STR + tl] = vv.y;
    }
    __syncthreads();
    #pragma unroll
    for (int i = 0; i < 16; i++) {
        int idx = tid + i * 256;            // 0..4095: (r, t2) half2 outputs
        int r  = idx >> 6;
        int t2 = idx & 63;
        __half2 hv = __floats2half2_rn(vsm[r * VR_STR + 2 * t2],
                                       vsm[r * VR_STR + 2 * t2 + 1]);
        *reinterpret_cast<uint32_t*>(
            &g_vt[((size_t)z * HD_ + r) * T_ + t0 + 2 * t2]) = h2u(hv);
    }
}

// ---------------- FP16 tensor-core GEMM (QKV + proj) -------------------------
// C[M,Ntot] = A[M,K] @ Bt[Ntot,K]^T + bias. A,Bt fp16 row-major, C f32.
// CTA tile 128x128, BK=64 halfs, 256 threads, warp tile 64x32.
#define GM_STR   72                         // smem row stride (halfs)
#define GM_TSZ   (128 * GM_STR)             // 9216 halfs per tile
#define GM_STG   (2 * GM_TSZ)               // A+B per stage
#define GM_SMEM  (2 * GM_STG * 2)           // bytes = 73728

__global__ __launch_bounds__(256)
void tgemm_h(const __half* __restrict__ A, const __half* __restrict__ Bt,
             const float* __restrict__ bias, float* __restrict__ C,
             int K, int Ntot)
{
    extern __shared__ __half smh[];
    const int bm = blockIdx.y * 128;
    const int bn = blockIdx.x * 128;
    const int tid  = threadIdx.x;
    const int warp = tid >> 5;
    const int lane = tid & 31;
    const int grp  = lane >> 2;
    const int qd   = lane & 3;
    const int wm   = (warp & 1) * 64;
    const int wn   = (warp >> 1) * 32;

    float acc[4][4][4];
    #pragma unroll
    for (int i = 0; i < 4; i++)
        #pragma unroll
        for (int j = 0; j < 4; j++)
            #pragma unroll
            for (int r = 0; r < 4; r++) acc[i][j][r] = 0.f;

    auto load_tiles = [&](int k0, int s) {
        __half* as = smh + s * GM_STG;
        __half* bs = as + GM_TSZ;
        #pragma unroll
        for (int i = 0; i < 4; i++) {
            int idx = tid + i * 256;          // 0..1023
            int m  = idx >> 3;
            int kc = (idx & 7) * 8;
            cp_async16(&as[m * GM_STR + kc], &A [(size_t)(bm + m) * K + k0 + kc]);
        }
        #pragma unroll
        for (int i = 0; i < 4; i++) {
            int idx = tid + i * 256;
            int n  = idx >> 3;
            int kc = (idx & 7) * 8;
            cp_async16(&bs[n * GM_STR + kc], &Bt[(size_t)(bn + n) * K + k0 + kc]);
        }
        asm volatile("cp.async.commit_group;\n");
    };

    auto compute = [&](int s) {
        const __half* as = smh + s * GM_STG;
        const __half* bs = as + GM_TSZ;
        #pragma unroll
        for (int ks = 0; ks < 4; ks++) {
            const int kb = ks * 16;
            uint32_t af[4][4], bf[4][2];
            #pragma unroll
            for (int mi = 0; mi < 4; mi++) {
                int r = wm + mi * 16 + grp;
                af[mi][0] = *(const uint32_t*)&as[(r    ) * GM_STR + kb + 2 * qd    ];
                af[mi][1] = *(const uint32_t*)&as[(r + 8) * GM_STR + kb + 2 * qd    ];
                af[mi][2] = *(const uint32_t*)&as[(r    ) * GM_STR + kb + 2 * qd + 8];
                af[mi][3] = *(const uint32_t*)&as[(r + 8) * GM_STR + kb + 2 * qd + 8];
            }
            #pragma unroll
            for (int ni = 0; ni < 4; ni++) {
                int n = wn + ni * 8 + grp;
                bf[ni][0] = *(const uint32_t*)&bs[n * GM_STR + kb + 2 * qd    ];
                bf[ni][1] = *(const uint32_t*)&bs[n * GM_STR + kb + 2 * qd + 8];
            }
            #pragma unroll
            for (int mi = 0; mi < 4; mi++)
                #pragma unroll
                for (int ni = 0; ni < 4; ni++)
                    mma_fp16(acc[mi][ni], af[mi][0], af[mi][1], af[mi][2], af[mi][3],
                             bf[ni][0], bf[ni][1]);
        }
    };

    const int NC = K / 64;                  // 16
    load_tiles(0, 0);
    for (int c = 0; c < NC; c++) {
        if (c + 1 < NC) {
            load_tiles((c + 1) * 64, (c + 1) & 1);
            asm volatile("cp.async.wait_group 1;\n");
        } else {
            asm volatile("cp.async.wait_group 0;\n");
        }
        __syncthreads();
        compute(c & 1);
        __syncthreads();
    }

    #pragma unroll
    for (int mi = 0; mi < 4; mi++) {
        int r = bm + wm + mi * 16 + grp;
        #pragma unroll
        for (int ni = 0; ni < 4; ni++) {
            int cl = bn + wn + ni * 8 + 2 * qd;
            float bb0 = bias[cl], bb1 = bias[cl + 1];
            float2 v0 = { acc[mi][ni][0] + bb0, acc[mi][ni][1] + bb1 };
            float2 v1 = { acc[mi][ni][2] + bb0, acc[mi][ni][3] + bb1 };
            *reinterpret_cast<float2*>(&C[(size_t)(r    ) * Ntot + cl]) = v0;
            *reinterpret_cast<float2*>(&C[(size_t)(r + 8) * Ntot + cl]) = v1;
        }
    }
}

// ---------------- fused flash attention (fp16 mma) ---------------------------
// grid (T_/128, BH), 256 threads = 8 warps; each warp 16 Q rows x full KV tile.
// smem (halfs): K0[128*72] K1 VT0[64*136] VT1
#define FKS     72
#define FVS     136
#define F_KS0   0
#define F_KS1   (128 * FKS)                  // 9216
#define F_VT0   (2 * 128 * FKS)              // 18432
#define F_VT1   (F_VT0 + 64 * FVS)           // 27136
#define F_TOTH  (F_VT0 + 2 * 64 * FVS)       // 35840 halfs
#define F_SMEM  (F_TOTH * 2)                 // 71680 bytes

__global__ __launch_bounds__(256, 1)
void flash_kernel()
{
    extern __shared__ __half smh[];
    const int z  = blockIdx.y;
    const int qt = blockIdx.x;
    const int b  = z >> 4;
    const int h  = z & 15;
    const __half* Qg = g_q  + (size_t)z * T_ * HD_ + (size_t)qt * 128 * HD_;
    const __half* Kg = g_k  + (size_t)z * T_ * HD_;
    const __half* Vg = g_vt + (size_t)z * HD_ * T_;

    const int tid  = threadIdx.x;
    const int warp = tid >> 5;
    const int lane = tid & 31;
    const int grp  = lane >> 2;
    const int qd   = lane & 3;

    // ---- stage Q in K-stage0, extract fragments ----
    {
        __half* qs = smh + F_KS0;
        #pragma unroll
        for (int i = 0; i < 4; i++) {
            int idx = tid + i * 256;
            int r = idx >> 3;
            int c = (idx & 7) * 8;
            cp_async16(&qs[r * FKS + c], &Qg[r * HD_ + c]);
        }
        asm volatile("cp.async.commit_group;\ncp.async.wait_group 0;\n");
        __syncthreads();
    }
    uint32_t qf[4][4];
    {
        const __half* qs = smh + F_KS0;
        const int r0 = warp * 16 + grp;
        #pragma unroll
        for (int ks = 0; ks < 4; ks++) {
            const int kb = ks * 16;
            qf[ks][0] = *(const uint32_t*)&qs[(r0    ) * FKS + kb + 2 * qd    ];
            qf[ks][1] = *(const uint32_t*)&qs[(r0 + 8) * FKS + kb + 2 * qd    ];
            qf[ks][2] = *(const uint32_t*)&qs[(r0    ) * FKS + kb + 2 * qd + 8];
            qf[ks][3] = *(const uint32_t*)&qs[(r0 + 8) * FKS + kb + 2 * qd + 8];
        }
    }
    __syncthreads();

    auto load_kv = [&](int kv0, int buf) {
        __half* ks = smh + (buf ? F_KS1 : F_KS0);
        __half* vs = smh + (buf ? F_VT1 : F_VT0);
        #pragma unroll
        for (int i = 0; i < 4; i++) {
            int idx = tid + i * 256;
            int r = idx >> 3;
            int c = (idx & 7) * 8;
            cp_async16(&ks[r * FKS + c], &Kg[(size_t)(kv0 + r) * HD_ + c]);
        }
        #pragma unroll
        for (int i = 0; i < 4; i++) {
            int idx = tid + i * 256;
            int r = idx >> 4;                // 0..63 (hd row)
            int c = (idx & 15) * 8;          // 0..120 (kv col)
            cp_async16(&vs[r * FVS + c], &Vg[(size_t)r * T_ + kv0 + c]);
        }
        asm volatile("cp.async.commit_group;\n");
    };

    load_kv(0, 0);

    float m0 = -INFINITY, m1 = -INFINITY;
    float l0 = 0.f, l1 = 0.f;
    float o[8][4];
    #pragma unroll
    for (int ni = 0; ni < 8; ni++)
        #pragma unroll
        for (int r = 0; r < 4; r++) o[ni][r] = 0.f;

    const int NIT = T_ / 128;               // 16
    for (int it = 0; it < NIT; it++) {
        const int buf = it & 1;
        asm volatile("cp.async.wait_group 0;\n");
        __syncthreads();
        if (it + 1 < NIT) load_kv((it + 1) * 128, buf ^ 1);

        const __half* ks = smh + (buf ? F_KS1 : F_KS0);
        const __half* vs = smh + (buf ? F_VT1 : F_VT0);

        // ---- S = Q @ K^T: 16 n-tiles x 4 k-steps ----
        float sacc[16][4];
        #pragma unroll
        for (int ni = 0; ni < 16; ni++)
            #pragma unroll
            for (int r = 0; r < 4; r++) sacc[ni][r] = 0.f;

        #pragma unroll
        for (int kst = 0; kst < 4; kst++) {
            const int kb = kst * 16;
            #pragma unroll
            for (int ni = 0; ni < 16; ni++) {
                const __half* kr = &ks[(ni * 8 + grp) * FKS + kb + 2 * qd];
                uint32_t b0 = *(const uint32_t*)(kr);
                uint32_t b1 = *(const uint32_t*)(kr + 8);
                mma_fp16(sacc[ni], qf[kst][0], qf[kst][1], qf[kst][2], qf[kst][3], b0, b1);
            }
        }

        // ---- online softmax (rows grp, grp+8; quad reduction) ----
        float xm0 = -INFINITY, xm1 = -INFINITY;
        #pragma unroll
        for (int ni = 0; ni < 16; ni++) {
            xm0 = fmaxf(xm0, fmaxf(sacc[ni][0], sacc[ni][1]));
            xm1 = fmaxf(xm1, fmaxf(sacc[ni][2], sacc[ni][3]));
        }
        xm0 = fmaxf(xm0, __shfl_xor_sync(~0u, xm0, 1));
        xm0 = fmaxf(xm0, __shfl_xor_sync(~0u, xm0, 2));
        xm1 = fmaxf(xm1, __shfl_xor_sync(~0u, xm1, 1));
        xm1 = fmaxf(xm1, __shfl_xor_sync(~0u, xm1, 2));

        const float nm0 = fmaxf(m0, xm0);
        const float nm1 = fmaxf(m1, xm1);
        const float f0 = __expf(m0 - nm0);
        const float f1 = __expf(m1 - nm1);
        m0 = nm0; m1 = nm1;

        float s0 = 0.f, s1 = 0.f;
        #pragma unroll
        for (int ni = 0; ni < 16; ni++) {
            sacc[ni][0] = __expf(sacc[ni][0] - nm0);
            sacc[ni][1] = __expf(sacc[ni][1] - nm0);
            sacc[ni][2] = __expf(sacc[ni][2] - nm1);
            sacc[ni][3] = __expf(sacc[ni][3] - nm1);
            s0 += sacc[ni][0] + sacc[ni][1];
            s1 += sacc[ni][2] + sacc[ni][3];
        }
        s0 += __shfl_xor_sync(~0u, s0, 1);
        s0 += __shfl_xor_sync(~0u, s0, 2);
        s1 += __shfl_xor_sync(~0u, s1, 1);
        s1 += __shfl_xor_sync(~0u, s1, 2);
        l0 = l0 * f0 + s0;
        l1 = l1 * f1 + s1;

        #pragma unroll
        for (int ni = 0; ni < 8; ni++) {
            o[ni][0] *= f0; o[ni][1] *= f0;
            o[ni][2] *= f1; o[ni][3] *= f1;
        }

        // ---- O += P @ V : P A-frags repacked directly from C-frags ----
        #pragma unroll
        for (int j = 0; j < 8; j++) {
            const int kb = j * 16;
            uint32_t a0 = h2u(__floats2half2_rn(sacc[2*j  ][0], sacc[2*j  ][1]));
            uint32_t a1 = h2u(__floats2half2_rn(sacc[2*j  ][2], sacc[2*j  ][3]));
            uint32_t a2 = h2u(__floats2half2_rn(sacc[2*j+1][0], sacc[2*j+1][1]));
            uint32_t a3 = h2u(__floats2half2_rn(sacc[2*j+1][2], sacc[2*j+1][3]));
            #pragma unroll
            for (int ni = 0; ni < 8; ni++) {
                const __half* vr = &vs[(ni * 8 + grp) * FVS + kb + 2 * qd];
                uint32_t b0 = *(const uint32_t*)(vr);
                uint32_t b1 = *(const uint32_t*)(vr + 8);
                mma_fp16(o[ni], a0, a1, a2, a3, b0, b1);
            }
        }
    }

    // ---- normalize + fused merge_heads write (fp16 ctx for proj) ----
    const float i0 = 1.f / l0;
    const float i1 = 1.f / l1;
    const int t0 = qt * 128 + warp * 16 + grp;
    #pragma unroll
    for (int ni = 0; ni < 8; ni++) {
        int col = h * HD_ + ni * 8 + 2 * qd;
        __half2 v0 = __floats2half2_rn(o[ni][0] * i0, o[ni][1] * i0);
        __half2 v1 = __floats2half2_rn(o[ni][2] * i1, o[ni][3] * i1);
        *reinterpret_cast<uint32_t*>(&g_ctx[(size_t)(b * T_ + t0    ) * D_ + col]) = h2u(v0);
        *reinterpret_cast<uint32_t*>(&g_ctx[(size_t)(b * T_ + t0 + 8) * D_ + col]) = h2u(v1);
    }
}

// ---------------- launch ----------------------------------------------------
extern "C" void kernel_launch(void* const* d_in, const int* in_sizes, int n_in,
                              void* d_out, int out_size)
{
    const float* x      = (const float*)d_in[0];
    const float* W_attn = (const float*)d_in[1];
    const float* b_attn = (const float*)d_in[2];
    const float* W_proj = (const float*)d_in[3];
    const float* b_proj = (const float*)d_in[4];
    float* out = (float*)d_out;

    float  *qkv;
    __half *xh, *wah, *wph, *ctx;
    cudaGetSymbolAddress((void**)&qkv, g_qkv);
    cudaGetSymbolAddress((void**)&xh,  g_xh);
    cudaGetSymbolAddress((void**)&wah, g_wah);
    cudaGetSymbolAddress((void**)&wph, g_wph);
    cudaGetSymbolAddress((void**)&ctx, g_ctx);

    cudaFuncSetAttribute((const void*)tgemm_h,
                         cudaFuncAttributeMaxDynamicSharedMemorySize, GM_SMEM);
    cudaFuncSetAttribute((const void*)flash_kernel,
                         cudaFuncAttributeMaxDynamicSharedMemorySize, F_SMEM);

    // 0. fp16 conversions / weight transposes
    f2h_kernel<<<(BT * D_ / 4 + 255) / 256, 256>>>(
        (const float4*)x, (uint2*)xh, BT * D_ / 4);
    {
        dim3 grid(3 * D_ / 32, D_ / 32);
        transpose_h_kernel<<<grid, dim3(32, 8)>>>(W_attn, wah, D_, 3 * D_);
    }
    {
        dim3 grid(D_ / 32, D_ / 32);
        transpose_h_kernel<<<grid, dim3(32, 8)>>>(W_proj, wph, D_, D_);
    }

    // 1. RoPE tables
    rope_tables_kernel<<<(T_ * 32) / 256, 256>>>();

    // 2. QKV GEMM: [8192,1024] @ [1024,3072]^T-form + b_attn -> f32
    {
        dim3 grid(3 * D_ / 128, BT / 128);
        tgemm_h<<<grid, 256, GM_SMEM>>>(xh, wah, b_attn, qkv, D_, 3 * D_);
    }

    // 3. split heads + RoPE (+ V transpose), fp16 outputs
    {
        dim3 grid(T_ / 128, BH);
        rope_apply_kernel<<<grid, 256>>>();
    }

    // 4-7. fused flash attention -> ctx (fp16, merged heads)
    {
        dim3 grid(T_ / 128, BH);
        flash_kernel<<<grid, 256, F_SMEM>>>();
    }

    // 8. output projection: [8192,1024] @ [1024,1024]^T-form + b_proj -> out
    {
        dim3 grid(D_ / 128, BT / 128);
        tgemm_h<<<grid, 256, GM_SMEM>>>(ctx, wph, b_proj, out, D_, D_);
    }
}